// round 1
// baseline (speedup 1.0000x reference)
#include <cuda_runtime.h>
#include <cstdint>

#define BSZ 4
#define SEQ 2048
#define DM  512
#define NH  8
#define DKH 64
#define MR  (BSZ * SEQ)   // 8192 flattened rows

// Scratch (allocation-free rule: __device__ globals)
__device__ float g_Qp[(size_t)MR * DM];
__device__ float g_Kp[(size_t)MR * DM];
__device__ float g_Vp[(size_t)MR * DM];
__device__ float g_Y [(size_t)MR * DM];

__device__ __forceinline__ float neg_inf_f() { return __int_as_float(0xff800000u); }

// ---------------------------------------------------------------------------
// Masked GEMM: Y[r][c] = rowmask[r] * sum_k X[r][k] * W[c][k]
// M = 8192 (rows), N = 512 (cols), K = 512.
// Block 64x64, 256 threads, 4x4 microtile, KT=16.
// Smem layout [row][k] with pitch 17: A reads broadcast, B reads 2-way.
// ---------------------------------------------------------------------------
__global__ __launch_bounds__(256) void gemm_xwt_rowmask(
    const float* __restrict__ X, const float* __restrict__ W,
    const float* __restrict__ rmask, float* __restrict__ Y)
{
    __shared__ float Xs[64][17];
    __shared__ float Ws[64][17];

    const int tid  = threadIdx.x;
    const int tx   = tid & 15;
    const int ty   = tid >> 4;
    const int row0 = blockIdx.y << 6;
    const int col0 = blockIdx.x << 6;

    // loader mapping: each thread loads one float4 of X and one of W per tile
    const int lr = tid >> 2;          // 0..63
    const int lk = (tid & 3) << 2;    // 0,4,8,12

    const float* xg = X + (size_t)(row0 + lr) * DM + lk;
    const float* wg = W + (size_t)(col0 + lr) * DM + lk;

    float acc[4][4];
#pragma unroll
    for (int i = 0; i < 4; i++)
#pragma unroll
        for (int j = 0; j < 4; j++) acc[i][j] = 0.0f;

    for (int k0 = 0; k0 < DM; k0 += 16) {
        float4 xv = *(const float4*)(xg + k0);
        float4 wv = *(const float4*)(wg + k0);
        Xs[lr][lk + 0] = xv.x; Xs[lr][lk + 1] = xv.y;
        Xs[lr][lk + 2] = xv.z; Xs[lr][lk + 3] = xv.w;
        Ws[lr][lk + 0] = wv.x; Ws[lr][lk + 1] = wv.y;
        Ws[lr][lk + 2] = wv.z; Ws[lr][lk + 3] = wv.w;
        __syncthreads();

#pragma unroll
        for (int k = 0; k < 16; k++) {
            float a[4], b[4];
#pragma unroll
            for (int i = 0; i < 4; i++) a[i] = Xs[(ty << 2) + i][k];
#pragma unroll
            for (int j = 0; j < 4; j++) b[j] = Ws[(tx << 2) + j][k];
#pragma unroll
            for (int i = 0; i < 4; i++)
#pragma unroll
                for (int j = 0; j < 4; j++) acc[i][j] = fmaf(a[i], b[j], acc[i][j]);
        }
        __syncthreads();
    }

#pragma unroll
    for (int i = 0; i < 4; i++) {
        const int r = row0 + (ty << 2) + i;
        const float mfac = rmask[r];
        float* yo = Y + (size_t)r * DM + col0 + (tx << 2);
#pragma unroll
        for (int j = 0; j < 4; j++) yo[j] = mfac * acc[i][j];
    }
}

// ---------------------------------------------------------------------------
// Flash-style attention per (64-query tile, head, batch).
// Reads g_Qp/g_Kp/g_Vp (pre-masked projections), writes g_Y (post-masked).
// Online softmax with -inf masking; attn*mask is a mathematical no-op.
// Dynamic smem: Qs, Ks, Vs, Ps each [64][65] floats = 66560 B total.
// ---------------------------------------------------------------------------
__global__ __launch_bounds__(256) void attn_kernel(
    const float* __restrict__ att_mas, const float* __restrict__ k_mas)
{
    extern __shared__ float sm[];
    float (*Qs)[65] = (float(*)[65])(sm);
    float (*Ks)[65] = (float(*)[65])(sm + 64 * 65);
    float (*Vs)[65] = (float(*)[65])(sm + 2 * 64 * 65);
    float (*Ps)[65] = (float(*)[65])(sm + 3 * 64 * 65);

    const int tid = threadIdx.x;
    const int tx  = tid & 15;
    const int ty  = tid >> 4;
    const int q0  = blockIdx.x << 6;
    const int h   = blockIdx.y;
    const int b   = blockIdx.z;

    const float NEGINF = neg_inf_f();

    // Load Q tile (64 queries x 64 head-dims)
    {
        const float* Qbase = g_Qp + ((size_t)b * SEQ + q0) * DM + h * DKH;
        for (int i = tid; i < 64 * 16; i += 256) {
            const int r = i >> 4;
            const int c = (i & 15) << 2;
            float4 v = *(const float4*)(Qbase + (size_t)r * DM + c);
            Qs[r][c + 0] = v.x; Qs[r][c + 1] = v.y;
            Qs[r][c + 2] = v.z; Qs[r][c + 3] = v.w;
        }
    }

    float m[4], l[4], acc[4][4];
#pragma unroll
    for (int i = 0; i < 4; i++) {
        m[i] = NEGINF; l[i] = 0.0f;
#pragma unroll
        for (int j = 0; j < 4; j++) acc[i][j] = 0.0f;
    }

    const float* amb = att_mas + (size_t)b * SEQ * SEQ;

    for (int kt = 0; kt < SEQ / 64; kt++) {
        const int kk0 = kt << 6;
        const float* Kbase = g_Kp + ((size_t)b * SEQ + kk0) * DM + h * DKH;
        const float* Vbase = g_Vp + ((size_t)b * SEQ + kk0) * DM + h * DKH;

        __syncthreads();  // previous PV reads done before overwriting tiles
        for (int i = tid; i < 64 * 16; i += 256) {
            const int r = i >> 4;
            const int c = (i & 15) << 2;
            float4 kv = *(const float4*)(Kbase + (size_t)r * DM + c);
            Ks[r][c + 0] = kv.x; Ks[r][c + 1] = kv.y;
            Ks[r][c + 2] = kv.z; Ks[r][c + 3] = kv.w;
            float4 vv = *(const float4*)(Vbase + (size_t)r * DM + c);
            Vs[r][c + 0] = vv.x; Vs[r][c + 1] = vv.y;
            Vs[r][c + 2] = vv.z; Vs[r][c + 3] = vv.w;
        }
        __syncthreads();

        // S = (Q K^T) * 1/sqrt(dk), masked
        float s[4][4];
#pragma unroll
        for (int i = 0; i < 4; i++)
#pragma unroll
            for (int j = 0; j < 4; j++) s[i][j] = 0.0f;

#pragma unroll 8
        for (int d = 0; d < 64; d++) {
            float a[4], bb[4];
#pragma unroll
            for (int i = 0; i < 4; i++) a[i] = Qs[(ty << 2) + i][d];
#pragma unroll
            for (int j = 0; j < 4; j++) bb[j] = Ks[(tx << 2) + j][d];
#pragma unroll
            for (int i = 0; i < 4; i++)
#pragma unroll
                for (int j = 0; j < 4; j++) s[i][j] = fmaf(a[i], bb[j], s[i][j]);
        }

#pragma unroll
        for (int i = 0; i < 4; i++) {
            const float4 mk = *(const float4*)(amb + (size_t)(q0 + (ty << 2) + i) * SEQ
                                               + kk0 + (tx << 2));
            s[i][0] = (mk.x != 0.0f) ? s[i][0] * 0.125f : NEGINF;
            s[i][1] = (mk.y != 0.0f) ? s[i][1] * 0.125f : NEGINF;
            s[i][2] = (mk.z != 0.0f) ? s[i][2] * 0.125f : NEGINF;
            s[i][3] = (mk.w != 0.0f) ? s[i][3] * 0.125f : NEGINF;
        }

        // row max across the 64-wide tile (16 lanes per row group)
        float rm[4];
#pragma unroll
        for (int i = 0; i < 4; i++) {
            rm[i] = fmaxf(fmaxf(s[i][0], s[i][1]), fmaxf(s[i][2], s[i][3]));
#pragma unroll
            for (int off = 8; off; off >>= 1)
                rm[i] = fmaxf(rm[i], __shfl_xor_sync(0xffffffffu, rm[i], off));
        }

        float alpha[4], mn[4], rs[4];
#pragma unroll
        for (int i = 0; i < 4; i++) {
            mn[i] = fmaxf(m[i], rm[i]);
            alpha[i] = (m[i] == mn[i]) ? 1.0f : __expf(m[i] - mn[i]);
            rs[i] = 0.0f;
#pragma unroll
            for (int j = 0; j < 4; j++) {
                float p = (s[i][j] == NEGINF) ? 0.0f : __expf(s[i][j] - mn[i]);
                s[i][j] = p;   // reuse s as P
                rs[i] += p;
            }
#pragma unroll
            for (int off = 8; off; off >>= 1)
                rs[i] += __shfl_xor_sync(0xffffffffu, rs[i], off);
            l[i] = l[i] * alpha[i] + rs[i];
            m[i] = mn[i];
#pragma unroll
            for (int j = 0; j < 4; j++) acc[i][j] *= alpha[i];
            // stage P
#pragma unroll
            for (int j = 0; j < 4; j++) Ps[(ty << 2) + i][(tx << 2) + j] = s[i][j];
        }
        __syncthreads();

        // O += P V
#pragma unroll 8
        for (int kk = 0; kk < 64; kk++) {
            float a[4], v[4];
#pragma unroll
            for (int i = 0; i < 4; i++) a[i] = Ps[(ty << 2) + i][kk];
#pragma unroll
            for (int j = 0; j < 4; j++) v[j] = Vs[kk][(tx << 2) + j];
#pragma unroll
            for (int i = 0; i < 4; i++)
#pragma unroll
                for (int j = 0; j < 4; j++) acc[i][j] = fmaf(a[i], v[j], acc[i][j]);
        }
    }

    // Epilogue: normalize, post-mask (k_mas indexed by QUERY position, per ref)
#pragma unroll
    for (int i = 0; i < 4; i++) {
        const int q = q0 + (ty << 2) + i;
        const float kmq = k_mas[(size_t)b * SEQ + q];
        const float invl = kmq / l[i];   // l > 0 guaranteed by forced self-edges
        float* yo = g_Y + ((size_t)b * SEQ + q) * DM + h * DKH + (tx << 2);
#pragma unroll
        for (int j = 0; j < 4; j++) yo[j] = acc[i][j] * invl;
    }
}

// ---------------------------------------------------------------------------
extern "C" void kernel_launch(void* const* d_in, const int* in_sizes, int n_in,
                              void* d_out, int out_size)
{
    (void)in_sizes; (void)n_in; (void)out_size;
    const float* Q   = (const float*)d_in[0];
    const float* K   = (const float*)d_in[1];
    const float* V   = (const float*)d_in[2];
    const float* qm  = (const float*)d_in[3];
    const float* km  = (const float*)d_in[4];
    const float* am  = (const float*)d_in[5];
    const float* WQ  = (const float*)d_in[6];
    const float* WK  = (const float*)d_in[7];
    const float* WV  = (const float*)d_in[8];
    const float* WO  = (const float*)d_in[9];
    float* out = (float*)d_out;

    float *Qp, *Kp, *Vp, *Y;
    cudaGetSymbolAddress((void**)&Qp, g_Qp);
    cudaGetSymbolAddress((void**)&Kp, g_Kp);
    cudaGetSymbolAddress((void**)&Vp, g_Vp);
    cudaGetSymbolAddress((void**)&Y,  g_Y);

    const dim3 ggrid(DM / 64, MR / 64);

    gemm_xwt_rowmask<<<ggrid, 256>>>(Q, WQ, qm, Qp);
    gemm_xwt_rowmask<<<ggrid, 256>>>(K, WK, km, Kp);
    gemm_xwt_rowmask<<<ggrid, 256>>>(V, WV, km, Vp);

    const int smem_bytes = 4 * 64 * 65 * (int)sizeof(float);  // 66560
    cudaFuncSetAttribute(attn_kernel, cudaFuncAttributeMaxDynamicSharedMemorySize,
                         smem_bytes);
    attn_kernel<<<dim3(SEQ / 64, NH, BSZ), 256, smem_bytes>>>(am, km);

    gemm_xwt_rowmask<<<ggrid, 256>>>(Y, WO, km, out);
}

// round 2
// speedup vs baseline: 3.0990x; 3.0990x over previous
#include <cuda_runtime.h>
#include <cstdint>

#define BSZ 4
#define SEQ 2048
#define DM  512
#define NH  8
#define DKH 64
#define MR  (BSZ * SEQ)   // 8192 flattened rows

// Scratch (allocation-free rule: __device__ globals)
__device__ float g_Qp[(size_t)MR * DM];
__device__ float g_Kp[(size_t)MR * DM];
__device__ float g_Vp[(size_t)MR * DM];
__device__ float g_Y [(size_t)MR * DM];

__device__ __forceinline__ float neg_inf_f() { return __int_as_float(0xff800000u); }

__device__ __forceinline__ uint32_t f2tf(float f) {
    uint32_t u;
    asm("cvt.rna.tf32.f32 %0, %1;" : "=r"(u) : "f"(f));
    return u;
}

// D += A @ B  (m16n8k8, tf32 in, f32 accum)
__device__ __forceinline__ void mma_tf32(float* c, const uint32_t* a, const uint32_t* b) {
    asm volatile(
        "mma.sync.aligned.m16n8k8.row.col.f32.tf32.tf32.f32 "
        "{%0,%1,%2,%3}, {%4,%5,%6,%7}, {%8,%9}, {%0,%1,%2,%3};\n"
        : "+f"(c[0]), "+f"(c[1]), "+f"(c[2]), "+f"(c[3])
        : "r"(a[0]), "r"(a[1]), "r"(a[2]), "r"(a[3]), "r"(b[0]), "r"(b[1]));
}

// ---------------------------------------------------------------------------
// TF32 masked GEMM: Y[r][c] = rowmask[r] * sum_k X[r][k] * W[c][k]
// M=8192, N=512, K=512. Block tile 128x128x32, 8 warps (2x4), warp tile 64x32.
// ---------------------------------------------------------------------------
__global__ __launch_bounds__(256) void gemm_tf32_rowmask(
    const float* __restrict__ X, const float* __restrict__ W,
    const float* __restrict__ rmask, float* __restrict__ Y)
{
    __shared__ uint32_t Xs[128][36];
    __shared__ uint32_t Ws[128][36];

    const int tid  = threadIdx.x;
    const int lane = tid & 31;
    const int wid  = tid >> 5;
    const int g    = lane >> 2;   // groupID 0..7
    const int tg   = lane & 3;    // thread-in-group 0..3
    const int wm   = wid >> 2;    // 0..1
    const int wn   = wid & 3;     // 0..3
    const int row0 = blockIdx.y << 7;
    const int col0 = blockIdx.x << 7;

    float c[4][4][4];
#pragma unroll
    for (int mi = 0; mi < 4; mi++)
#pragma unroll
        for (int nj = 0; nj < 4; nj++)
#pragma unroll
            for (int q = 0; q < 4; q++) c[mi][nj][q] = 0.0f;

    for (int k0 = 0; k0 < DM; k0 += 32) {
        __syncthreads();
#pragma unroll
        for (int t = 0; t < 4; t++) {
            const int idx = tid + (t << 8);          // 0..1023
            const int r   = idx >> 3;
            const int c4  = (idx & 7) << 2;
            float4 xv = *(const float4*)(X + (size_t)(row0 + r) * DM + k0 + c4);
            Xs[r][c4 + 0] = f2tf(xv.x); Xs[r][c4 + 1] = f2tf(xv.y);
            Xs[r][c4 + 2] = f2tf(xv.z); Xs[r][c4 + 3] = f2tf(xv.w);
            float4 wv = *(const float4*)(W + (size_t)(col0 + r) * DM + k0 + c4);
            Ws[r][c4 + 0] = f2tf(wv.x); Ws[r][c4 + 1] = f2tf(wv.y);
            Ws[r][c4 + 2] = f2tf(wv.z); Ws[r][c4 + 3] = f2tf(wv.w);
        }
        __syncthreads();

#pragma unroll
        for (int kk = 0; kk < 4; kk++) {
            uint32_t a[4][4], b[4][2];
            const int kb = kk << 3;
#pragma unroll
            for (int mi = 0; mi < 4; mi++) {
                const int rb = (wm << 6) + (mi << 4);
                a[mi][0] = Xs[rb + g    ][kb + tg];
                a[mi][1] = Xs[rb + g + 8][kb + tg];
                a[mi][2] = Xs[rb + g    ][kb + tg + 4];
                a[mi][3] = Xs[rb + g + 8][kb + tg + 4];
            }
#pragma unroll
            for (int nj = 0; nj < 4; nj++) {
                const int cb = (wn << 5) + (nj << 3);
                b[nj][0] = Ws[cb + g][kb + tg];
                b[nj][1] = Ws[cb + g][kb + tg + 4];
            }
#pragma unroll
            for (int mi = 0; mi < 4; mi++)
#pragma unroll
                for (int nj = 0; nj < 4; nj++) mma_tf32(c[mi][nj], a[mi], b[nj]);
        }
    }

#pragma unroll
    for (int mi = 0; mi < 4; mi++) {
        const int r1 = row0 + (wm << 6) + (mi << 4) + g;
        const int r2 = r1 + 8;
        const float m1 = rmask[r1];
        const float m2 = rmask[r2];
#pragma unroll
        for (int nj = 0; nj < 4; nj++) {
            const int cc = col0 + (wn << 5) + (nj << 3) + (tg << 1);
            float2 v1; v1.x = m1 * c[mi][nj][0]; v1.y = m1 * c[mi][nj][1];
            float2 v2; v2.x = m2 * c[mi][nj][2]; v2.y = m2 * c[mi][nj][3];
            *(float2*)(Y + (size_t)r1 * DM + cc) = v1;
            *(float2*)(Y + (size_t)r2 * DM + cc) = v2;
        }
    }
}

// ---------------------------------------------------------------------------
// TF32 flash attention. Block = 128 queries x (head, batch).
// 8 warps, each owns 16 query rows (FA2 split over M).
// Key/value tiles of 64. Online softmax in thread quads.
// Dynamic smem: Qs[128][68] Ks[64][68] Vs[64][72] Ps[128][68] = 105472 B.
// ---------------------------------------------------------------------------
__global__ __launch_bounds__(256) void attn_tf32(
    const float* __restrict__ att_mas, const float* __restrict__ k_mas)
{
    extern __shared__ uint32_t smbuf[];
    uint32_t (*Qs)[68] = (uint32_t(*)[68])(smbuf);
    uint32_t (*Ks)[68] = (uint32_t(*)[68])(smbuf + 128 * 68);
    uint32_t (*Vs)[72] = (uint32_t(*)[72])(smbuf + 128 * 68 + 64 * 68);
    uint32_t (*Ps)[68] = (uint32_t(*)[68])(smbuf + 128 * 68 + 64 * 68 + 64 * 72);

    const int tid  = threadIdx.x;
    const int lane = tid & 31;
    const int wid  = tid >> 5;    // 0..7
    const int g    = lane >> 2;
    const int tg   = lane & 3;
    const int q0   = blockIdx.x << 7;
    const int h    = blockIdx.y;
    const int b    = blockIdx.z;
    const int qrow = wid << 4;    // warp's first query row in tile

    const float NEGINF = neg_inf_f();

    // Load Q tile (128 x 64), convert tf32
    {
        const float* Qb = g_Qp + ((size_t)b * SEQ + q0) * DM + h * DKH;
#pragma unroll
        for (int t = 0; t < 8; t++) {
            const int idx = tid + (t << 8);       // 0..2047
            const int r   = idx >> 4;
            const int c4  = (idx & 15) << 2;
            float4 v = *(const float4*)(Qb + (size_t)r * DM + c4);
            Qs[r][c4 + 0] = f2tf(v.x); Qs[r][c4 + 1] = f2tf(v.y);
            Qs[r][c4 + 2] = f2tf(v.z); Qs[r][c4 + 3] = f2tf(v.w);
        }
    }

    float o[8][4];
#pragma unroll
    for (int dj = 0; dj < 8; dj++)
#pragma unroll
        for (int q = 0; q < 4; q++) o[dj][q] = 0.0f;
    float mrow0 = NEGINF, mrow1 = NEGINF, lrow0 = 0.0f, lrow1 = 0.0f;

    const float* amq = att_mas + (size_t)b * SEQ * SEQ;
    const int q1 = q0 + qrow + g;
    const int q2 = q1 + 8;

    for (int kt = 0; kt < SEQ / 64; kt++) {
        const int kk0 = kt << 6;
        __syncthreads();  // prior PV reads of Ks/Vs complete (also covers Qs on kt=0)
        {
            const float* Kb = g_Kp + ((size_t)b * SEQ + kk0) * DM + h * DKH;
            const float* Vb = g_Vp + ((size_t)b * SEQ + kk0) * DM + h * DKH;
#pragma unroll
            for (int t = 0; t < 4; t++) {
                const int idx = tid + (t << 8);   // 0..1023
                const int r   = idx >> 4;
                const int c4  = (idx & 15) << 2;
                float4 kv = *(const float4*)(Kb + (size_t)r * DM + c4);
                Ks[r][c4 + 0] = f2tf(kv.x); Ks[r][c4 + 1] = f2tf(kv.y);
                Ks[r][c4 + 2] = f2tf(kv.z); Ks[r][c4 + 3] = f2tf(kv.w);
                float4 vv = *(const float4*)(Vb + (size_t)r * DM + c4);
                Vs[r][c4 + 0] = f2tf(vv.x); Vs[r][c4 + 1] = f2tf(vv.y);
                Vs[r][c4 + 2] = f2tf(vv.z); Vs[r][c4 + 3] = f2tf(vv.w);
            }
        }
        __syncthreads();

        // S = Q @ K^T  (warp: 16 x 64, 8 n-blocks, 8 k8 steps)
        float s[8][4];
#pragma unroll
        for (int nj = 0; nj < 8; nj++)
#pragma unroll
            for (int q = 0; q < 4; q++) s[nj][q] = 0.0f;

#pragma unroll
        for (int kk = 0; kk < 8; kk++) {
            const int kb = kk << 3;
            uint32_t a[4];
            a[0] = Qs[qrow + g    ][kb + tg];
            a[1] = Qs[qrow + g + 8][kb + tg];
            a[2] = Qs[qrow + g    ][kb + tg + 4];
            a[3] = Qs[qrow + g + 8][kb + tg + 4];
#pragma unroll
            for (int nj = 0; nj < 8; nj++) {
                uint32_t bb[2];
                bb[0] = Ks[(nj << 3) + g][kb + tg];
                bb[1] = Ks[(nj << 3) + g][kb + tg + 4];
                mma_tf32(s[nj], a, bb);
            }
        }

        // Scale + mask
#pragma unroll
        for (int nj = 0; nj < 8; nj++) {
            const int ck = kk0 + (nj << 3) + (tg << 1);
            float2 m1 = *(const float2*)(amq + (size_t)q1 * SEQ + ck);
            float2 m2 = *(const float2*)(amq + (size_t)q2 * SEQ + ck);
            s[nj][0] = (m1.x != 0.0f) ? s[nj][0] * 0.125f : NEGINF;
            s[nj][1] = (m1.y != 0.0f) ? s[nj][1] * 0.125f : NEGINF;
            s[nj][2] = (m2.x != 0.0f) ? s[nj][2] * 0.125f : NEGINF;
            s[nj][3] = (m2.y != 0.0f) ? s[nj][3] * 0.125f : NEGINF;
        }

        // Row max (within thread, then across quad: lanes xor 1, xor 2)
        float rm0 = NEGINF, rm1 = NEGINF;
#pragma unroll
        for (int nj = 0; nj < 8; nj++) {
            rm0 = fmaxf(rm0, fmaxf(s[nj][0], s[nj][1]));
            rm1 = fmaxf(rm1, fmaxf(s[nj][2], s[nj][3]));
        }
        rm0 = fmaxf(rm0, __shfl_xor_sync(0xffffffffu, rm0, 1));
        rm0 = fmaxf(rm0, __shfl_xor_sync(0xffffffffu, rm0, 2));
        rm1 = fmaxf(rm1, __shfl_xor_sync(0xffffffffu, rm1, 1));
        rm1 = fmaxf(rm1, __shfl_xor_sync(0xffffffffu, rm1, 2));

        const float mn0 = fmaxf(mrow0, rm0);
        const float mn1 = fmaxf(mrow1, rm1);
        const float al0 = (mrow0 == mn0) ? 1.0f : __expf(mrow0 - mn0);
        const float al1 = (mrow1 == mn1) ? 1.0f : __expf(mrow1 - mn1);

        float rs0 = 0.0f, rs1 = 0.0f;
#pragma unroll
        for (int nj = 0; nj < 8; nj++) {
            float p0 = (s[nj][0] == NEGINF) ? 0.0f : __expf(s[nj][0] - mn0);
            float p1 = (s[nj][1] == NEGINF) ? 0.0f : __expf(s[nj][1] - mn0);
            float p2 = (s[nj][2] == NEGINF) ? 0.0f : __expf(s[nj][2] - mn1);
            float p3 = (s[nj][3] == NEGINF) ? 0.0f : __expf(s[nj][3] - mn1);
            rs0 += p0 + p1;
            rs1 += p2 + p3;
            const int pc = (nj << 3) + (tg << 1);
            Ps[qrow + g    ][pc + 0] = f2tf(p0);
            Ps[qrow + g    ][pc + 1] = f2tf(p1);
            Ps[qrow + g + 8][pc + 0] = f2tf(p2);
            Ps[qrow + g + 8][pc + 1] = f2tf(p3);
        }
        rs0 += __shfl_xor_sync(0xffffffffu, rs0, 1);
        rs0 += __shfl_xor_sync(0xffffffffu, rs0, 2);
        rs1 += __shfl_xor_sync(0xffffffffu, rs1, 1);
        rs1 += __shfl_xor_sync(0xffffffffu, rs1, 2);

        lrow0 = lrow0 * al0 + rs0;
        lrow1 = lrow1 * al1 + rs1;
        mrow0 = mn0;
        mrow1 = mn1;

#pragma unroll
        for (int dj = 0; dj < 8; dj++) {
            o[dj][0] *= al0; o[dj][1] *= al0;
            o[dj][2] *= al1; o[dj][3] *= al1;
        }
        __syncwarp();  // P stores visible to whole warp before A-frag reads

        // O += P @ V  (k over 64 keys = 8 k8 steps; 8 d-blocks of n8)
#pragma unroll
        for (int kk = 0; kk < 8; kk++) {
            const int kb = kk << 3;
            uint32_t a[4];
            a[0] = Ps[qrow + g    ][kb + tg];
            a[1] = Ps[qrow + g + 8][kb + tg];
            a[2] = Ps[qrow + g    ][kb + tg + 4];
            a[3] = Ps[qrow + g + 8][kb + tg + 4];
#pragma unroll
            for (int dj = 0; dj < 8; dj++) {
                uint32_t bb[2];
                bb[0] = Vs[kb + tg    ][(dj << 3) + g];
                bb[1] = Vs[kb + tg + 4][(dj << 3) + g];
                mma_tf32(o[dj], a, bb);
            }
        }
    }

    // Epilogue: normalize, post-mask (k_mas indexed by query pos, per reference)
    const float sc0 = k_mas[(size_t)b * SEQ + q1] / lrow0;
    const float sc1 = k_mas[(size_t)b * SEQ + q2] / lrow1;
    float* Y1 = g_Y + ((size_t)b * SEQ + q1) * DM + h * DKH;
    float* Y2 = g_Y + ((size_t)b * SEQ + q2) * DM + h * DKH;
#pragma unroll
    for (int dj = 0; dj < 8; dj++) {
        const int cc = (dj << 3) + (tg << 1);
        float2 v1; v1.x = o[dj][0] * sc0; v1.y = o[dj][1] * sc0;
        float2 v2; v2.x = o[dj][2] * sc1; v2.y = o[dj][3] * sc1;
        *(float2*)(Y1 + cc) = v1;
        *(float2*)(Y2 + cc) = v2;
    }
}

// ---------------------------------------------------------------------------
extern "C" void kernel_launch(void* const* d_in, const int* in_sizes, int n_in,
                              void* d_out, int out_size)
{
    (void)in_sizes; (void)n_in; (void)out_size;
    const float* Q   = (const float*)d_in[0];
    const float* K   = (const float*)d_in[1];
    const float* V   = (const float*)d_in[2];
    const float* qm  = (const float*)d_in[3];
    const float* km  = (const float*)d_in[4];
    const float* am  = (const float*)d_in[5];
    const float* WQ  = (const float*)d_in[6];
    const float* WK  = (const float*)d_in[7];
    const float* WV  = (const float*)d_in[8];
    const float* WO  = (const float*)d_in[9];
    float* out = (float*)d_out;

    float *Qp, *Kp, *Vp, *Y;
    cudaGetSymbolAddress((void**)&Qp, g_Qp);
    cudaGetSymbolAddress((void**)&Kp, g_Kp);
    cudaGetSymbolAddress((void**)&Vp, g_Vp);
    cudaGetSymbolAddress((void**)&Y,  g_Y);

    const dim3 ggrid(DM / 128, MR / 128);

    gemm_tf32_rowmask<<<ggrid, 256>>>(Q, WQ, qm, Qp);
    gemm_tf32_rowmask<<<ggrid, 256>>>(K, WK, km, Kp);
    gemm_tf32_rowmask<<<ggrid, 256>>>(V, WV, km, Vp);

    const int attn_smem = (128 * 68 + 64 * 68 + 64 * 72 + 128 * 68) * (int)sizeof(uint32_t);
    cudaFuncSetAttribute(attn_tf32, cudaFuncAttributeMaxDynamicSharedMemorySize,
                         attn_smem);
    attn_tf32<<<dim3(SEQ / 128, NH, BSZ), 256, attn_smem>>>(am, km);

    gemm_tf32_rowmask<<<ggrid, 256>>>(Y, WO, km, out);
}

// round 4
// speedup vs baseline: 3.2613x; 1.0524x over previous
#include <cuda_runtime.h>
#include <cstdint>

#define BSZ 4
#define SEQ 2048
#define DM  512
#define NH  8
#define DKH 64
#define MR  (BSZ * SEQ)   // 8192 flattened rows
#define MWORDS (SEQ / 32) // 64 mask words per row

// Scratch (allocation-free rule: __device__ globals)
__device__ float    g_Qp[(size_t)MR * DM];
__device__ float    g_Kp[(size_t)MR * DM];
__device__ float    g_Vp[(size_t)MR * DM];
__device__ float    g_Y [(size_t)MR * DM];
__device__ uint32_t g_mask[(size_t)BSZ * SEQ * MWORDS];

__device__ __forceinline__ float neg_inf_f() { return __int_as_float(0xff800000u); }

__device__ __forceinline__ uint32_t f2tf(float f) {
    uint32_t u;
    asm("cvt.rna.tf32.f32 %0, %1;" : "=r"(u) : "f"(f));
    return u;
}

__device__ __forceinline__ void mma_tf32(float* c, const uint32_t* a, const uint32_t* b) {
    asm volatile(
        "mma.sync.aligned.m16n8k8.row.col.f32.tf32.tf32.f32 "
        "{%0,%1,%2,%3}, {%4,%5,%6,%7}, {%8,%9}, {%0,%1,%2,%3};\n"
        : "+f"(c[0]), "+f"(c[1]), "+f"(c[2]), "+f"(c[3])
        : "r"(a[0]), "r"(a[1]), "r"(a[2]), "r"(a[3]), "r"(b[0]), "r"(b[1]));
}

__device__ __forceinline__ void ldsm4(uint32_t* r, uint32_t addr) {
    asm volatile("ldmatrix.sync.aligned.m8n8.x4.shared.b16 {%0,%1,%2,%3}, [%4];"
        : "=r"(r[0]), "=r"(r[1]), "=r"(r[2]), "=r"(r[3]) : "r"(addr));
}

__device__ __forceinline__ uint32_t smem_u32(const void* p) {
    return (uint32_t)__cvta_generic_to_shared(p);
}

// ---------------------------------------------------------------------------
// Pack att_mas (0.0/1.0 floats) into bits. One thread per element; ballot.
// ---------------------------------------------------------------------------
__global__ __launch_bounds__(256) void pack_mask(const float* __restrict__ am)
{
    const size_t idx = (size_t)blockIdx.x * 256 + threadIdx.x;
    const float v = am[idx];
    const unsigned bal = __ballot_sync(0xffffffffu, v != 0.0f);
    if ((threadIdx.x & 31) == 0) g_mask[idx >> 5] = bal;
}

// ---------------------------------------------------------------------------
// TF32 masked GEMM (unchanged from R2): Y[r][c] = rowmask[r]*sum_k X[r][k]W[c][k]
// ---------------------------------------------------------------------------
__global__ __launch_bounds__(256) void gemm_tf32_rowmask(
    const float* __restrict__ X, const float* __restrict__ W,
    const float* __restrict__ rmask, float* __restrict__ Y)
{
    __shared__ uint32_t Xs[128][36];
    __shared__ uint32_t Ws[128][36];

    const int tid  = threadIdx.x;
    const int lane = tid & 31;
    const int wid  = tid >> 5;
    const int g    = lane >> 2;
    const int tg   = lane & 3;
    const int wm   = wid >> 2;
    const int wn   = wid & 3;
    const int row0 = blockIdx.y << 7;
    const int col0 = blockIdx.x << 7;

    float c[4][4][4];
#pragma unroll
    for (int mi = 0; mi < 4; mi++)
#pragma unroll
        for (int nj = 0; nj < 4; nj++)
#pragma unroll
            for (int q = 0; q < 4; q++) c[mi][nj][q] = 0.0f;

    for (int k0 = 0; k0 < DM; k0 += 32) {
        __syncthreads();
#pragma unroll
        for (int t = 0; t < 4; t++) {
            const int idx = tid + (t << 8);
            const int r   = idx >> 3;
            const int c4  = (idx & 7) << 2;
            float4 xv = *(const float4*)(X + (size_t)(row0 + r) * DM + k0 + c4);
            Xs[r][c4 + 0] = f2tf(xv.x); Xs[r][c4 + 1] = f2tf(xv.y);
            Xs[r][c4 + 2] = f2tf(xv.z); Xs[r][c4 + 3] = f2tf(xv.w);
            float4 wv = *(const float4*)(W + (size_t)(col0 + r) * DM + k0 + c4);
            Ws[r][c4 + 0] = f2tf(wv.x); Ws[r][c4 + 1] = f2tf(wv.y);
            Ws[r][c4 + 2] = f2tf(wv.z); Ws[r][c4 + 3] = f2tf(wv.w);
        }
        __syncthreads();

#pragma unroll
        for (int kk = 0; kk < 4; kk++) {
            uint32_t a[4][4], b[4][2];
            const int kb = kk << 3;
#pragma unroll
            for (int mi = 0; mi < 4; mi++) {
                const int rb = (wm << 6) + (mi << 4);
                a[mi][0] = Xs[rb + g    ][kb + tg];
                a[mi][1] = Xs[rb + g + 8][kb + tg];
                a[mi][2] = Xs[rb + g    ][kb + tg + 4];
                a[mi][3] = Xs[rb + g + 8][kb + tg + 4];
            }
#pragma unroll
            for (int nj = 0; nj < 4; nj++) {
                const int cb = (wn << 5) + (nj << 3);
                b[nj][0] = Ws[cb + g][kb + tg];
                b[nj][1] = Ws[cb + g][kb + tg + 4];
            }
#pragma unroll
            for (int mi = 0; mi < 4; mi++)
#pragma unroll
                for (int nj = 0; nj < 4; nj++) mma_tf32(c[mi][nj], a[mi], b[nj]);
        }
    }

#pragma unroll
    for (int mi = 0; mi < 4; mi++) {
        const int r1 = row0 + (wm << 6) + (mi << 4) + g;
        const int r2 = r1 + 8;
        const float m1 = rmask[r1];
        const float m2 = rmask[r2];
#pragma unroll
        for (int nj = 0; nj < 4; nj++) {
            const int cc = col0 + (wn << 5) + (nj << 3) + (tg << 1);
            float2 v1; v1.x = m1 * c[mi][nj][0]; v1.y = m1 * c[mi][nj][1];
            float2 v2; v2.x = m2 * c[mi][nj][2]; v2.y = m2 * c[mi][nj][3];
            *(float2*)(Y + (size_t)r1 * DM + cc) = v1;
            *(float2*)(Y + (size_t)r2 * DM + cc) = v2;
        }
    }
}

// ---------------------------------------------------------------------------
// TF32 flash attention, LDSM fragment loads + bitmask.
// Block = 128 queries x (head, batch); 8 warps x 16 query rows.
// Smem: Qs[128][68] Ks[64][68] Vs[64][72] Ps[128][68] = 105472 B.
// ---------------------------------------------------------------------------
__global__ __launch_bounds__(256) void attn_tf32(const float* __restrict__ k_mas)
{
    extern __shared__ uint32_t smbuf[];
    uint32_t (*Qs)[68] = (uint32_t(*)[68])(smbuf);
    uint32_t (*Ks)[68] = (uint32_t(*)[68])(smbuf + 128 * 68);
    uint32_t (*Vs)[72] = (uint32_t(*)[72])(smbuf + 128 * 68 + 64 * 68);
    uint32_t (*Ps)[68] = (uint32_t(*)[68])(smbuf + 128 * 68 + 64 * 68 + 64 * 72);

    const int tid  = threadIdx.x;
    const int lane = tid & 31;
    const int wid  = tid >> 5;
    const int g    = lane >> 2;
    const int tg   = lane & 3;
    const int q0   = blockIdx.x << 7;
    const int h    = blockIdx.y;
    const int b    = blockIdx.z;
    const int qrow = wid << 4;

    const float NEGINF = neg_inf_f();

    // per-lane LDSM base addresses (byte addresses in shared space)
    // A pattern (Q/P): row = base + (lane&15), col = ((lane>>4)<<2)
    const uint32_t qsA = smem_u32(Qs) + (((qrow + (lane & 15)) * 68 + ((lane >> 4) << 2)) << 2);
    const uint32_t psA = smem_u32(Ps) + (((qrow + (lane & 15)) * 68 + ((lane >> 4) << 2)) << 2);
    // B pattern (K): row = (lane&7) + ((lane&16)>>1), col = (lane&8)>>1
    const uint32_t ksB = smem_u32(Ks) +
        (((((lane & 7) + ((lane & 16) >> 1)) * 68) + ((lane & 8) >> 1)) << 2);

    // Load Q tile (128 x 64), convert tf32
    {
        const float* Qb = g_Qp + ((size_t)b * SEQ + q0) * DM + h * DKH;
#pragma unroll
        for (int t = 0; t < 8; t++) {
            const int idx = tid + (t << 8);
            const int r   = idx >> 4;
            const int c4  = (idx & 15) << 2;
            float4 v = *(const float4*)(Qb + (size_t)r * DM + c4);
            uint4 u; u.x = f2tf(v.x); u.y = f2tf(v.y); u.z = f2tf(v.z); u.w = f2tf(v.w);
            *(uint4*)&Qs[r][c4] = u;
        }
    }

    float o[8][4];
#pragma unroll
    for (int dj = 0; dj < 8; dj++)
#pragma unroll
        for (int q = 0; q < 4; q++) o[dj][q] = 0.0f;
    float mrow0 = NEGINF, mrow1 = NEGINF, lrow0 = 0.0f, lrow1 = 0.0f;

    const int q1 = q0 + qrow + g;
    const int q2 = q1 + 8;
    const uint32_t* mrow1p = g_mask + ((size_t)b * SEQ + q1) * MWORDS;
    const uint32_t* mrow2p = g_mask + ((size_t)b * SEQ + q2) * MWORDS;

    for (int kt = 0; kt < SEQ / 64; kt++) {
        const int kk0 = kt << 6;
        __syncthreads();  // prior PV reads of Ks/Vs complete (covers Qs on kt=0)
        {
            const float* Kb = g_Kp + ((size_t)b * SEQ + kk0) * DM + h * DKH;
            const float* Vb = g_Vp + ((size_t)b * SEQ + kk0) * DM + h * DKH;
#pragma unroll
            for (int t = 0; t < 4; t++) {
                const int idx = tid + (t << 8);
                const int r   = idx >> 4;
                const int c4  = (idx & 15) << 2;
                float4 kv = *(const float4*)(Kb + (size_t)r * DM + c4);
                uint4 ku; ku.x = f2tf(kv.x); ku.y = f2tf(kv.y); ku.z = f2tf(kv.z); ku.w = f2tf(kv.w);
                *(uint4*)&Ks[r][c4] = ku;
                float4 vv = *(const float4*)(Vb + (size_t)r * DM + c4);
                uint4 vu; vu.x = f2tf(vv.x); vu.y = f2tf(vv.y); vu.z = f2tf(vv.z); vu.w = f2tf(vv.w);
                *(uint4*)&Vs[r][c4] = vu;
            }
        }
        __syncthreads();

        // S = Q @ K^T
        float s[8][4];
#pragma unroll
        for (int nj = 0; nj < 8; nj++)
#pragma unroll
            for (int q = 0; q < 4; q++) s[nj][q] = 0.0f;

#pragma unroll
        for (int kk = 0; kk < 8; kk++) {
            const int kb = kk << 3;
            uint32_t a[4];
            ldsm4(a, qsA + (kb << 2));
#pragma unroll
            for (int njp = 0; njp < 4; njp++) {
                uint32_t bb[4];
                ldsm4(bb, ksB + ((njp * 16 * 68 + kb) << 2));
                mma_tf32(s[2 * njp],     a, bb);
                mma_tf32(s[2 * njp + 1], a, bb + 2);
            }
        }

        // Scale + bitmask
        const uint2 mw1 = *(const uint2*)(mrow1p + (kt << 1));
        const uint2 mw2 = *(const uint2*)(mrow2p + (kt << 1));
#pragma unroll
        for (int nj = 0; nj < 8; nj++) {
            const int j0 = (nj << 3) + (tg << 1);   // even, j0 and j0+1 same word
            const uint32_t w1 = (j0 & 32) ? mw1.y : mw1.x;
            const uint32_t w2 = (j0 & 32) ? mw2.y : mw2.x;
            const int bi = j0 & 31;
            s[nj][0] = ((w1 >> bi) & 1u)       ? s[nj][0] * 0.125f : NEGINF;
            s[nj][1] = ((w1 >> (bi + 1)) & 1u) ? s[nj][1] * 0.125f : NEGINF;
            s[nj][2] = ((w2 >> bi) & 1u)       ? s[nj][2] * 0.125f : NEGINF;
            s[nj][3] = ((w2 >> (bi + 1)) & 1u) ? s[nj][3] * 0.125f : NEGINF;
        }

        // Row max across quad
        float rm0 = NEGINF, rm1 = NEGINF;
#pragma unroll
        for (int nj = 0; nj < 8; nj++) {
            rm0 = fmaxf(rm0, fmaxf(s[nj][0], s[nj][1]));
            rm1 = fmaxf(rm1, fmaxf(s[nj][2], s[nj][3]));
        }
        rm0 = fmaxf(rm0, __shfl_xor_sync(0xffffffffu, rm0, 1));
        rm0 = fmaxf(rm0, __shfl_xor_sync(0xffffffffu, rm0, 2));
        rm1 = fmaxf(rm1, __shfl_xor_sync(0xffffffffu, rm1, 1));
        rm1 = fmaxf(rm1, __shfl_xor_sync(0xffffffffu, rm1, 2));

        const float mn0 = fmaxf(mrow0, rm0);
        const float mn1 = fmaxf(mrow1, rm1);
        const float al0 = (mrow0 == mn0) ? 1.0f : __expf(mrow0 - mn0);
        const float al1 = (mrow1 == mn1) ? 1.0f : __expf(mrow1 - mn1);

        float rs0 = 0.0f, rs1 = 0.0f;
#pragma unroll
        for (int nj = 0; nj < 8; nj++) {
            float p0 = (s[nj][0] == NEGINF) ? 0.0f : __expf(s[nj][0] - mn0);
            float p1 = (s[nj][1] == NEGINF) ? 0.0f : __expf(s[nj][1] - mn0);
            float p2 = (s[nj][2] == NEGINF) ? 0.0f : __expf(s[nj][2] - mn1);
            float p3 = (s[nj][3] == NEGINF) ? 0.0f : __expf(s[nj][3] - mn1);
            rs0 += p0 + p1;
            rs1 += p2 + p3;
            const int pc = (nj << 3) + (tg << 1);
            uint2 u1; u1.x = f2tf(p0); u1.y = f2tf(p1);
            uint2 u2; u2.x = f2tf(p2); u2.y = f2tf(p3);
            *(uint2*)&Ps[qrow + g    ][pc] = u1;
            *(uint2*)&Ps[qrow + 8 + g][pc] = u2;
        }
        rs0 += __shfl_xor_sync(0xffffffffu, rs0, 1);
        rs0 += __shfl_xor_sync(0xffffffffu, rs0, 2);
        rs1 += __shfl_xor_sync(0xffffffffu, rs1, 1);
        rs1 += __shfl_xor_sync(0xffffffffu, rs1, 2);

        lrow0 = lrow0 * al0 + rs0;
        lrow1 = lrow1 * al1 + rs1;
        mrow0 = mn0;
        mrow1 = mn1;

#pragma unroll
        for (int dj = 0; dj < 8; dj++) {
            o[dj][0] *= al0; o[dj][1] *= al0;
            o[dj][2] *= al1; o[dj][3] *= al1;
        }
        __syncwarp();  // P stores visible within warp before LDSM A reads

        // O += P @ V
#pragma unroll
        for (int kk = 0; kk < 8; kk++) {
            const int kb = kk << 3;
            uint32_t a[4];
            ldsm4(a, psA + (kb << 2));
#pragma unroll
            for (int dj = 0; dj < 8; dj++) {
                uint32_t bb[2];
                bb[0] = Vs[kb + tg    ][(dj << 3) + g];
                bb[1] = Vs[kb + tg + 4][(dj << 3) + g];
                mma_tf32(o[dj], a, bb);
            }
        }
    }

    // Epilogue: normalize, post-mask (k_mas indexed by query pos, per reference)
    const float sc0 = k_mas[(size_t)b * SEQ + q1] / lrow0;
    const float sc1 = k_mas[(size_t)b * SEQ + q2] / lrow1;
    float* Y1 = g_Y + ((size_t)b * SEQ + q1) * DM + h * DKH;
    float* Y2 = g_Y + ((size_t)b * SEQ + q2) * DM + h * DKH;
#pragma unroll
    for (int dj = 0; dj < 8; dj++) {
        const int cc = (dj << 3) + (tg << 1);
        float2 v1; v1.x = o[dj][0] * sc0; v1.y = o[dj][1] * sc0;
        float2 v2; v2.x = o[dj][2] * sc1; v2.y = o[dj][3] * sc1;
        *(float2*)(Y1 + cc) = v1;
        *(float2*)(Y2 + cc) = v2;
    }
}

// ---------------------------------------------------------------------------
extern "C" void kernel_launch(void* const* d_in, const int* in_sizes, int n_in,
                              void* d_out, int out_size)
{
    (void)in_sizes; (void)n_in; (void)out_size;
    const float* Q   = (const float*)d_in[0];
    const float* K   = (const float*)d_in[1];
    const float* V   = (const float*)d_in[2];
    const float* qm  = (const float*)d_in[3];
    const float* km  = (const float*)d_in[4];
    const float* am  = (const float*)d_in[5];
    const float* WQ  = (const float*)d_in[6];
    const float* WK  = (const float*)d_in[7];
    const float* WV  = (const float*)d_in[8];
    const float* WO  = (const float*)d_in[9];
    float* out = (float*)d_out;

    float *Qp, *Kp, *Vp, *Y;
    cudaGetSymbolAddress((void**)&Qp, g_Qp);
    cudaGetSymbolAddress((void**)&Kp, g_Kp);
    cudaGetSymbolAddress((void**)&Vp, g_Vp);
    cudaGetSymbolAddress((void**)&Y,  g_Y);

    const dim3 ggrid(DM / 128, MR / 128);

    pack_mask<<<(BSZ * SEQ * SEQ) / 256, 256>>>(am);
    gemm_tf32_rowmask<<<ggrid, 256>>>(Q, WQ, qm, Qp);
    gemm_tf32_rowmask<<<ggrid, 256>>>(K, WK, km, Kp);
    gemm_tf32_rowmask<<<ggrid, 256>>>(V, WV, km, Vp);

    const int attn_smem = (128 * 68 + 64 * 68 + 64 * 72 + 128 * 68) * (int)sizeof(uint32_t);
    cudaFuncSetAttribute(attn_tf32, cudaFuncAttributeMaxDynamicSharedMemorySize,
                         attn_smem);
    attn_tf32<<<dim3(SEQ / 128, NH, BSZ), 256, attn_smem>>>(km);

    gemm_tf32_rowmask<<<ggrid, 256>>>(Y, WO, km, out);
}